// round 9
// baseline (speedup 1.0000x reference)
#include <cuda_runtime.h>

// Potential_6347961663538 — Gaussian form-factor splatting onto a 128x128 grid.
//
// out[b,i,j] = sum_a sum_f (ff_a·4π/ff_b)[a,f] *
//              exp(-π·(4π/ff_b)[a,f] · ((j-64-c0[b,a])² + (i-64-c1[b,a])²))
//
// π·invb = 4π²/ff_b >= 19.74, so any term with per-axis |d| > 3.5 underflows
// fp32 exp to exactly 0 — identical to the zeros the reference adds. A 7x7
// window around round(coord) reproduces every nonzero fp32 term.
//
// R9: single-node ROW GATHER, no grid barrier, no global atomics.
// 512 blocks = (batch, row). Each block owns one output row: it scans the
// batch's 2048 atoms (warp-local: 256 atoms/warp, ballot-compacted into a
// private smem queue — no block-wide counters or phase syncs), processes
// hit×pixel lane-jobs (5 form factors inline), accumulates into a 128-float
// smem row via shared atomics, and writes the row with plain STG. The
// poisoned output is fully overwritten -> memset node deleted (measured
// two-node graph overhead: ~3.4us; single-node: 0.13us).

#define SIDELEN 128
#define NATOM   2048
#define NB      4
#define NF      5
#define RAD     3
#define WIN     7
#define NWARP   8
#define THREADS (NWARP * 32)
#define QCAP    256            // worst case: every atom of the warp hits

__device__ __forceinline__ float ex2_approx(float x) {
    float r;
    asm("ex2.approx.f32 %0, %1;" : "=f"(r) : "f"(x));
    return r;
}

__global__ void __launch_bounds__(THREADS) potential_rowgather_kernel(
    const float* __restrict__ coords,   // [NB, NATOM, 3]
    const float* __restrict__ ff_a,     // [NATOM, NF]
    const float* __restrict__ ff_b,     // [NATOM, NF]
    float* __restrict__ out)            // [NB, SIDELEN, SIDELEN]
{
    __shared__ float s_row[SIDELEN];
    __shared__ float s_qc0 [NWARP][QCAP];
    __shared__ float s_qdy2[NWARP][QCAP];
    __shared__ int   s_qa  [NWARP][QCAP];

    const int b = blockIdx.x >> 7;            // batch
    const int r = blockIdx.x & 127;           // owned output row
    const int t = threadIdx.x;
    const int w = t >> 5;
    const int lane = t & 31;

    if (t < SIDELEN) s_row[t] = 0.0f;
    __syncthreads();

    // ---- Phase A: warp-local scan of 256 atoms, ballot-compact hits ----
    const float* cb = coords + ((size_t)b << 11) * 3;
    const float frow = (float)(r - SIDELEN / 2);
    int nq = 0;
    #pragma unroll
    for (int rd = 0; rd < 8; ++rd) {
        const int a  = (w << 8) + (rd << 5) + lane;
        const float c0 = __ldg(&cb[a * 3 + 0]);
        const float c1 = __ldg(&cb[a * 3 + 1]);
        const int ic = __float2int_rn(c1);
        const int jc = __float2int_rn(c0);
        // row window of atom = [ic+61, ic+67]; column window overlaps grid
        const bool hit = ((unsigned)(r - (ic + 61)) <= 2u * RAD) &&
                         ((unsigned)(jc + 67) <= 133u);
        const unsigned mask = __ballot_sync(0xffffffffu, hit);
        if (hit) {
            const int pos = nq + __popc(mask & ((1u << lane) - 1u));
            const float dy = frow - c1;
            s_qc0 [w][pos] = c0;
            s_qdy2[w][pos] = dy * dy;
            s_qa  [w][pos] = a;
        }
        nq += __popc(mask);
    }
    __syncwarp();

    // ---- Phase B: lane-jobs = (hit, pixel); 5 form factors inline ----
    const int jobs = nq * WIN;
    for (int base = 0; base < jobs; base += 32) {
        const int j = base + lane;
        if (j < jobs) {
            const int h  = (int)(((unsigned)j * 9363u) >> 16);   // j / 7
            const int px = j - h * WIN;
            const float c0  = s_qc0 [w][h];
            const float dy2 = s_qdy2[w][h];
            const int   a   = s_qa  [w][h];
            const int jc = __float2int_rn(c0);
            const float dx = (float)(jc - RAD + px) - c0;
            const int col  = jc + 61 + px;
            const float dd = fmaf(dx, dx, dy2);
            const float tt = -56.9553183f * dd;     // -(4π²·log2e)·dd
            const float* pa = &ff_a[a * NF];
            const float* pb = &ff_b[a * NF];
            float s = 0.0f;
            #pragma unroll
            for (int f = 0; f < NF; ++f) {
                const float inv = __frcp_rn(__ldg(&pb[f]));
                const float e   = ex2_approx(tt * inv);
                s = fmaf((__ldg(&pa[f]) * 12.56637061f) * inv, e, s);
            }
            if ((unsigned)col < SIDELEN && s != 0.0f)
                atomicAdd(&s_row[col], s);
        }
    }
    __syncthreads();

    // ---- Phase C: plain coalesced store of the owned row ----
    if (t < SIDELEN)
        out[(b << 14) + (r << 7) + t] = s_row[t];
}

extern "C" void kernel_launch(void* const* d_in, const int* in_sizes, int n_in,
                              void* d_out, int out_size) {
    const float* coords = (const float*)d_in[0];
    const float* ff_a   = (const float*)d_in[1];
    const float* ff_b   = (const float*)d_in[2];
    float* out = (float*)d_out;

    potential_rowgather_kernel<<<NB * SIDELEN, THREADS>>>(coords, ff_a, ff_b, out);
}

// round 10
// speedup vs baseline: 1.6589x; 1.6589x over previous
#include <cuda_runtime.h>

// Potential_6347961663538 — Gaussian form-factor splatting onto a 128x128 grid.
//
// out[b,i,j] = sum_a sum_f (ff_a·4π/ff_b)[a,f] *
//              exp(-π·(4π/ff_b)[a,f] · ((j-64-c0[b,a])² + (i-64-c1[b,a])²))
//
// π·invb = 4π²/ff_b >= 19.74: per-axis |d| > 3.5 underflows fp32 exp to
// exactly 0 (same zeros the reference adds), so a 7x7 window around
// round(coord) reproduces every nonzero fp32 term.
//
// R10: single-node ROW GATHER v2. 512 blocks = (batch, row); each block owns
// one output row and overwrites it with plain STG (no memset node: measured
// two-node graph overhead ~3.4us vs 0.13us single-node). R9's 25us failure
// was per-job constant reloads (10 scattered LDG + 5 rcp per lane-job) and a
// serialized scan. Fixes:
//   (1) scan preloads all 16 coord values (MLP=16) before the ballot rounds;
//   (2) compute processes 4 hits/round with 8 lanes/hit: lane k<5 loads ONE
//       coalesced ff pair and does ONE divide; 10 intra-group shuffles
//       broadcast (p2,coef); lanes k<7 each do one pixel (5 EX2 + 5 FMA).
// Worst block (center row, ~570 hits) ~18 rounds x ~120cyc.

#define SIDELEN 128
#define NATOM   2048
#define NB      4
#define NF      5
#define RAD     3
#define WIN     7
#define NWARP   8
#define THREADS (NWARP * 32)
#define QCAP    256

__device__ __forceinline__ float ex2_approx(float x) {
    float r;
    asm("ex2.approx.f32 %0, %1;" : "=f"(r) : "f"(x));
    return r;
}

__global__ void __launch_bounds__(THREADS) potential_rowgather2_kernel(
    const float* __restrict__ coords,   // [NB, NATOM, 3]
    const float* __restrict__ ff_a,     // [NATOM, NF]
    const float* __restrict__ ff_b,     // [NATOM, NF]
    float* __restrict__ out)            // [NB, SIDELEN, SIDELEN]
{
    __shared__ float s_row[SIDELEN];
    __shared__ float s_qc0[NWARP][QCAP];
    __shared__ float s_qd2[NWARP][QCAP];
    __shared__ int   s_qa [NWARP][QCAP];

    const int b    = blockIdx.x >> 7;         // batch
    const int r    = blockIdx.x & 127;        // owned output row
    const int t    = threadIdx.x;
    const int w    = t >> 5;
    const int lane = t & 31;

    if (t < SIDELEN) s_row[t] = 0.0f;
    __syncthreads();

    // ---- Phase A: scan 256 atoms/warp. Batch all loads first (MLP=16),
    //      then ballot-compact into the warp-private queue. ----
    const float* cb = coords + ((size_t)b << 11) * 3;
    const float frow = (float)(r - SIDELEN / 2);

    float c0v[8], c1v[8];
    #pragma unroll
    for (int rd = 0; rd < 8; ++rd) {
        const int a = (w << 8) + (rd << 5) + lane;
        c0v[rd] = __ldg(&cb[a * 3 + 0]);
        c1v[rd] = __ldg(&cb[a * 3 + 1]);
    }

    int nq = 0;
    #pragma unroll
    for (int rd = 0; rd < 8; ++rd) {
        const int a  = (w << 8) + (rd << 5) + lane;
        const int ic = __float2int_rn(c1v[rd]);
        const int jc = __float2int_rn(c0v[rd]);
        // row-window [ic+61, ic+67] contains r, and col-window hits the grid
        const bool hit = ((unsigned)(r - ic - 61) <= 2u * RAD) &&
                         ((unsigned)(jc + 67) <= 133u);
        const unsigned mask = __ballot_sync(0xffffffffu, hit);
        if (hit) {
            const int pos = nq + __popc(mask & ((1u << lane) - 1u));
            const float dy = frow - c1v[rd];
            s_qc0[w][pos] = c0v[rd];
            s_qd2[w][pos] = dy * dy;
            s_qa [w][pos] = a;
        }
        nq += __popc(mask);
    }
    __syncwarp();

    // ---- Phase B: 4 hits per round, 8 lanes per hit.
    //      k = lane&7: role (f-loader if k<5, pixel-computer if k<7). ----
    const int k  = lane & 7;
    const int g  = lane >> 3;          // hit slot within round
    const int gb = lane & 24;          // group base lane for shuffles

    for (int base = 0; base < nq; base += 4) {
        const int h  = base + g;
        const int hc = (h < nq) ? h : (nq - 1);    // clamp: keep loads safe
        const float c0 = s_qc0[w][hc];
        const float d2 = s_qd2[w][hc];
        const int   a  = s_qa [w][hc];

        // loader role: one (p2, coef) pair per lane k<5
        float p2l = 0.0f, cfl = 0.0f;
        if (k < NF) {
            const float fb  = __ldg(&ff_b[a * NF + k]);
            const float fa  = __ldg(&ff_a[a * NF + k]);
            const float inv = __fdividef(1.0f, fb);
            p2l = -56.9553183f * inv;           // -(4π²·log2e)/ff_b
            cfl = fa * 12.56637061f * inv;      // ff_a·4π/ff_b
        }
        const float p20 = __shfl_sync(0xffffffffu, p2l, gb + 0);
        const float p21 = __shfl_sync(0xffffffffu, p2l, gb + 1);
        const float p22 = __shfl_sync(0xffffffffu, p2l, gb + 2);
        const float p23 = __shfl_sync(0xffffffffu, p2l, gb + 3);
        const float p24 = __shfl_sync(0xffffffffu, p2l, gb + 4);
        const float cf0 = __shfl_sync(0xffffffffu, cfl, gb + 0);
        const float cf1 = __shfl_sync(0xffffffffu, cfl, gb + 1);
        const float cf2 = __shfl_sync(0xffffffffu, cfl, gb + 2);
        const float cf3 = __shfl_sync(0xffffffffu, cfl, gb + 3);
        const float cf4 = __shfl_sync(0xffffffffu, cfl, gb + 4);

        // pixel role: window column k (k<7)
        const int   jc = __float2int_rn(c0);
        const float dx = (float)(jc - RAD + k) - c0;
        const float dd = fmaf(dx, dx, d2);
        float s =            cf0 * ex2_approx(p20 * dd);
        s = fmaf(cf1, ex2_approx(p21 * dd), s);
        s = fmaf(cf2, ex2_approx(p22 * dd), s);
        s = fmaf(cf3, ex2_approx(p23 * dd), s);
        s = fmaf(cf4, ex2_approx(p24 * dd), s);

        const int col = jc + 61 + k;
        if (h < nq && k < WIN && (unsigned)col < SIDELEN && s != 0.0f)
            atomicAdd(&s_row[col], s);
    }
    __syncthreads();

    // ---- Phase C: plain coalesced store of the owned row ----
    if (t < SIDELEN)
        out[(b << 14) + (r << 7) + t] = s_row[t];
}

extern "C" void kernel_launch(void* const* d_in, const int* in_sizes, int n_in,
                              void* d_out, int out_size) {
    const float* coords = (const float*)d_in[0];
    const float* ff_a   = (const float*)d_in[1];
    const float* ff_b   = (const float*)d_in[2];
    float* out = (float*)d_out;

    potential_rowgather2_kernel<<<NB * SIDELEN, THREADS>>>(coords, ff_a, ff_b, out);
}

// round 11
// speedup vs baseline: 2.8787x; 1.7353x over previous
#include <cuda_runtime.h>

// Potential_6347961663538 — Gaussian form-factor splatting onto a 128x128 grid.
//
// out[b,i,j] = sum_a sum_f (ff_a·4π/ff_b)[a,f] *
//              exp(-π·(4π/ff_b)[a,f] · ((j-64-c0)² + (i-64-c1)²))
//
// π·invb = 4π²/ff_b >= 19.74: per-axis |d| > 3.5 underflows fp32 exp to
// exactly 0 (the same zeros the reference adds), so a 7x7 window around
// round(coord) reproduces every nonzero fp32 term.
//
// R11: single-node fused zero+scatter. R8's in-kernel grid barrier failed
// because 1024-block CTA-distribution skew (~5K cyc) was pure spin time.
// Fix: 128 blocks x 512 threads (1 CTA/SM, <=148 -> single wave GUARANTEED
// by __launch_bounds__(512,1)), so distribution skew ~hundreds of cycles.
// Each warp computes 4 atoms (R6 inner math, all input loads hoisted for
// MLP) entirely into registers BETWEEN barrier-arrive and barrier-wait
// (~1.4K cyc of compute >> skew: the wait is hidden), then fires its 8
// pre-resolved REDs after release. Zero-init: each block overwrites its
// exclusive 512-float slice; fence.gpu + monotonic-counter barrier orders
// all zeroing before any RED. Two-node graph overhead was measured at
// ~3.4us vs 0.13us single-node — that delta is the prize.

#define SIDELEN 128
#define NATOM   2048
#define NB      4
#define NF      5
#define RAD     3
#define WIN     7
#define THREADS 512
#define GRID    128
#define ATOMS_W 4              // atoms per warp

__device__ unsigned g_bar = 0; // monotonic arrival counter (state, not guard)

__device__ __forceinline__ float ex2_approx(float x) {
    float r;
    asm("ex2.approx.f32 %0, %1;" : "=f"(r) : "f"(x));
    return r;
}

__device__ __forceinline__ unsigned ld_acquire(const unsigned* p) {
    unsigned v;
    asm volatile("ld.acquire.gpu.u32 %0, [%1];" : "=r"(v) : "l"(p) : "memory");
    return v;
}

__global__ void __launch_bounds__(THREADS, 1) potential_fused128_kernel(
    const float* __restrict__ coords,   // [NB, NATOM, 3]
    const float* __restrict__ ff_a,     // [NATOM, NF]
    const float* __restrict__ ff_b,     // [NATOM, NF]
    float* __restrict__ out)            // [NB, SIDELEN, SIDELEN]
{
    const int t    = threadIdx.x;
    const int w    = t >> 5;
    const int lane = t & 31;
    const int gw   = blockIdx.x * (THREADS / 32) + w;  // 0..2047
    const int b    = gw >> 9;                          // batch
    const int aloc = (gw & 511) * ATOMS_W;             // atom index in [0,2048)

    // ---- hoisted input loads (max MLP; latency overlaps zero+barrier) ----
    float c0v[ATOMS_W], c1v[ATOMS_W];
    #pragma unroll
    for (int k = 0; k < ATOMS_W; ++k) {
        const int ci = (gw * ATOMS_W + k) * 3;         // coords incl. batch
        c0v[k] = __ldg(&coords[ci + 0]);
        c1v[k] = __ldg(&coords[ci + 1]);
    }
    // lanes 0..19: (atom k = lane/5, factor f = lane%5)
    float p2l = 0.0f, cfl = 0.0f;
    if (lane < ATOMS_W * NF) {
        const int k = lane / NF;
        const int f = lane - k * NF;
        const float fb  = __ldg(&ff_b[(aloc + k) * NF + f]);
        const float fa  = __ldg(&ff_a[(aloc + k) * NF + f]);
        const float inv = __fdividef(1.0f, fb);
        p2l = -56.9553183f * inv;        // -(4π²·log2e)/ff_b
        cfl = fa * 12.56637061f * inv;   // ff_a·4π/ff_b
    }

    // ---- zero this block's exclusive 512-float slice ----
    out[(blockIdx.x << 9) + t] = 0.0f;
    __syncthreads();

    // ---- barrier arrive (thread 0) ----
    unsigned target = 0;
    if (t == 0) {
        __threadfence();                                // release zero stores
        const unsigned old = atomicAdd(&g_bar, 1u);
        target = old - (old % GRID) + GRID;             // same in every block
    }

    // ---- compute 4 atoms x 2 pixel-jobs into registers (hides the wait) ----
    const int wi0 = lane / WIN, wj0 = lane - wi0 * WIN;  // job 0: pixel = lane
    const int pp  = lane + 32;                            // job 1: pixel = lane+32
    const int wi1 = pp / WIN,   wj1 = pp - wi1 * WIN;
    const bool v1 = pp < WIN * WIN;

    float sv[2 * ATOMS_W];
    int   iv[2 * ATOMS_W];                 // packed out index, or -1

    #pragma unroll
    for (int k = 0; k < ATOMS_W; ++k) {
        const float p20 = __shfl_sync(0xffffffffu, p2l, k * NF + 0);
        const float p21 = __shfl_sync(0xffffffffu, p2l, k * NF + 1);
        const float p22 = __shfl_sync(0xffffffffu, p2l, k * NF + 2);
        const float p23 = __shfl_sync(0xffffffffu, p2l, k * NF + 3);
        const float p24 = __shfl_sync(0xffffffffu, p2l, k * NF + 4);
        const float cf0 = __shfl_sync(0xffffffffu, cfl, k * NF + 0);
        const float cf1 = __shfl_sync(0xffffffffu, cfl, k * NF + 1);
        const float cf2 = __shfl_sync(0xffffffffu, cfl, k * NF + 2);
        const float cf3 = __shfl_sync(0xffffffffu, cfl, k * NF + 3);
        const float cf4 = __shfl_sync(0xffffffffu, cfl, k * NF + 4);

        const int jc = __float2int_rn(c0v[k]);
        const int ic = __float2int_rn(c1v[k]);
        const float fx = (float)(jc - RAD) - c0v[k];
        const float fy = (float)(ic - RAD) - c1v[k];
        const int jb = jc + SIDELEN / 2 - RAD;
        const int ib = ic + SIDELEN / 2 - RAD;

        {   // job 0
            const float dx = fx + (float)wj0, dy = fy + (float)wi0;
            const float dd = fmaf(dx, dx, dy * dy);
            float s =            cf0 * ex2_approx(p20 * dd);
            s = fmaf(cf1, ex2_approx(p21 * dd), s);
            s = fmaf(cf2, ex2_approx(p22 * dd), s);
            s = fmaf(cf3, ex2_approx(p23 * dd), s);
            s = fmaf(cf4, ex2_approx(p24 * dd), s);
            const int i = ib + wi0, j = jb + wj0;
            const bool ok = (unsigned)i < SIDELEN && (unsigned)j < SIDELEN &&
                            s != 0.0f;
            sv[2 * k]     = s;
            iv[2 * k]     = ok ? ((b << 14) + (i << 7) + j) : -1;
        }
        {   // job 1
            const float dx = fx + (float)wj1, dy = fy + (float)wi1;
            const float dd = fmaf(dx, dx, dy * dy);
            float s =            cf0 * ex2_approx(p20 * dd);
            s = fmaf(cf1, ex2_approx(p21 * dd), s);
            s = fmaf(cf2, ex2_approx(p22 * dd), s);
            s = fmaf(cf3, ex2_approx(p23 * dd), s);
            s = fmaf(cf4, ex2_approx(p24 * dd), s);
            const int i = ib + wi1, j = jb + wj1;
            const bool ok = v1 && (unsigned)i < SIDELEN &&
                            (unsigned)j < SIDELEN && s != 0.0f;
            sv[2 * k + 1] = s;
            iv[2 * k + 1] = ok ? ((b << 14) + (i << 7) + j) : -1;
        }
    }

    // ---- barrier wait + block release ----
    if (t == 0) {
        while (ld_acquire(&g_bar) < target)
            __nanosleep(32);
    }
    __syncthreads();

    // ---- fire the pre-resolved REDs ----
    #pragma unroll
    for (int q = 0; q < 2 * ATOMS_W; ++q)
        if (iv[q] >= 0)
            atomicAdd(&out[iv[q]], sv[q]);
}

extern "C" void kernel_launch(void* const* d_in, const int* in_sizes, int n_in,
                              void* d_out, int out_size) {
    const float* coords = (const float*)d_in[0];
    const float* ff_a   = (const float*)d_in[1];
    const float* ff_b   = (const float*)d_in[2];
    float* out = (float*)d_out;

    potential_fused128_kernel<<<GRID, THREADS>>>(coords, ff_a, ff_b, out);
}